// round 2
// baseline (speedup 1.0000x reference)
#include <cuda_runtime.h>
#include <cstdint>
#include <cstdio>

// Problem constants
#define BB 8
#define SS 2048
#define DD 1024
#define HH 8
#define CH 128            // CHUNK = D/H
#define GG (BB*HH)        // 64 groups after raw-view reshape
#define MM (BB*SS)        // 16384 rows for projection GEMMs
#define SCALE 0.03125f    // 1024^-0.5
#define LN_EPS 1e-5f

// ---------------- scratch (device globals; allocation-free) ----------------
__device__ float g_Q[(size_t)MM * DD];
__device__ float g_K[(size_t)MM * DD];   // reused as proj output after attention
__device__ float g_V[(size_t)MM * DD];
__device__ float g_ctx[(size_t)MM * DD];

// ---------------- helpers ----------------
__device__ __forceinline__ uint32_t f2tf32(float f) {
    uint32_t r;
    asm("cvt.rna.tf32.f32 %0, %1;" : "=r"(r) : "f"(f));
    return r;
}

__device__ __forceinline__ void mma_tf32(float c[4], const uint32_t a[4], const uint32_t b[2]) {
    asm volatile(
        "mma.sync.aligned.m16n8k8.row.col.f32.tf32.tf32.f32 "
        "{%0,%1,%2,%3}, {%4,%5,%6,%7}, {%8,%9}, {%0,%1,%2,%3};\n"
        : "+f"(c[0]), "+f"(c[1]), "+f"(c[2]), "+f"(c[3])
        : "r"(a[0]), "r"(a[1]), "r"(a[2]), "r"(a[3]), "r"(b[0]), "r"(b[1]));
}

// ---------------- GEMM: C[M,N] = A[M,K] @ W[N,K]^T  (M=16384,N=1024,K=1024) ----------------
// CTA tile 128x128, K-step 32. 8 warps (4m x 2n), warp tile 32x64.
__global__ __launch_bounds__(256) void gemm_xwT(const float* __restrict__ A,
                                                const float* __restrict__ W,
                                                float* __restrict__ C) {
    __shared__ uint32_t As[128 * 33];
    __shared__ uint32_t Ws[128 * 33];

    const int tid  = threadIdx.x;
    const int warp = tid >> 5;
    const int lane = tid & 31;
    const int gid  = lane >> 2;   // 0..7
    const int t4   = lane & 3;    // 0..3
    const int wm   = warp & 3;    // 0..3
    const int wn   = warp >> 2;   // 0..1

    const int mBase = blockIdx.y * 128;
    const int nBase = blockIdx.x * 128;

    float acc[2][8][4];
#pragma unroll
    for (int mi = 0; mi < 2; mi++)
#pragma unroll
        for (int nj = 0; nj < 8; nj++)
#pragma unroll
            for (int q = 0; q < 4; q++) acc[mi][nj][q] = 0.0f;

    const int col4 = (tid & 7) * 4;   // k offset (float4)
    const int row0 = tid >> 3;        // 0..31

    for (int kb = 0; kb < DD; kb += 32) {
#pragma unroll
        for (int w = 0; w < 4; w++) {
            const int r = row0 + w * 32;
            float4 va = *(const float4*)(A + (size_t)(mBase + r) * DD + kb + col4);
            As[r * 33 + col4 + 0] = f2tf32(va.x);
            As[r * 33 + col4 + 1] = f2tf32(va.y);
            As[r * 33 + col4 + 2] = f2tf32(va.z);
            As[r * 33 + col4 + 3] = f2tf32(va.w);
            float4 vw = *(const float4*)(W + (size_t)(nBase + r) * DD + kb + col4);
            Ws[r * 33 + col4 + 0] = f2tf32(vw.x);
            Ws[r * 33 + col4 + 1] = f2tf32(vw.y);
            Ws[r * 33 + col4 + 2] = f2tf32(vw.z);
            Ws[r * 33 + col4 + 3] = f2tf32(vw.w);
        }
        __syncthreads();

#pragma unroll
        for (int kk = 0; kk < 4; kk++) {
            uint32_t afr[2][4];
#pragma unroll
            for (int mi = 0; mi < 2; mi++) {
                const int r = wm * 32 + mi * 16 + gid;
                afr[mi][0] = As[r * 33 + kk * 8 + t4];
                afr[mi][1] = As[(r + 8) * 33 + kk * 8 + t4];
                afr[mi][2] = As[r * 33 + kk * 8 + t4 + 4];
                afr[mi][3] = As[(r + 8) * 33 + kk * 8 + t4 + 4];
            }
            uint32_t bfr[8][2];
#pragma unroll
            for (int nj = 0; nj < 8; nj++) {
                const int c = wn * 64 + nj * 8 + gid;
                bfr[nj][0] = Ws[c * 33 + kk * 8 + t4];
                bfr[nj][1] = Ws[c * 33 + kk * 8 + t4 + 4];
            }
#pragma unroll
            for (int mi = 0; mi < 2; mi++)
#pragma unroll
                for (int nj = 0; nj < 8; nj++) mma_tf32(acc[mi][nj], afr[mi], bfr[nj]);
        }
        __syncthreads();
    }

    // epilogue
#pragma unroll
    for (int mi = 0; mi < 2; mi++) {
        const int r = mBase + wm * 32 + mi * 16 + gid;
#pragma unroll
        for (int nj = 0; nj < 8; nj++) {
            const int c = nBase + wn * 64 + nj * 8 + t4 * 2;
            C[(size_t)r * DD + c]           = acc[mi][nj][0];
            C[(size_t)r * DD + c + 1]       = acc[mi][nj][1];
            C[(size_t)(r + 8) * DD + c]     = acc[mi][nj][2];
            C[(size_t)(r + 8) * DD + c + 1] = acc[mi][nj][3];
        }
    }
}

// ---------------- Flash-style attention ----------------
// Grid: (16 q-tiles, 64 groups). Block 256 (8 warps); each warp owns 16 q-rows.
// smem: Qs[128x132], Ks[128x132] (reused for P), Vs[128x132], tf32 bits.
#define ATT_STRIDE 132
#define ATT_SMEM_BYTES (3 * 128 * ATT_STRIDE * 4)

__global__ void __launch_bounds__(256, 1)
attn_kernel(const float* __restrict__ Q, const float* __restrict__ K,
            const float* __restrict__ V, float* __restrict__ O) {
    extern __shared__ uint32_t sm[];
    uint32_t* Qs = sm;
    uint32_t* Ks = sm + 128 * ATT_STRIDE;
    uint32_t* Vs = sm + 2 * 128 * ATT_STRIDE;

    const int tid  = threadIdx.x;
    const int warp = tid >> 5;
    const int lane = tid & 31;
    const int gid  = lane >> 2;
    const int t4   = lane & 3;

    const int g  = blockIdx.y;
    const int qt = blockIdx.x;

    const float* Qg = Q + (size_t)g * SS * CH + (size_t)qt * 128 * CH;
    const float* Kg = K + (size_t)g * SS * CH;
    const float* Vg = V + (size_t)g * SS * CH;
    float*       Og = O + (size_t)g * SS * CH + (size_t)qt * 128 * CH;

    // load Q tile (scaled, tf32)
    {
        const int col4 = (tid & 31) * 4;
        const int row0 = tid >> 5;
#pragma unroll
        for (int w = 0; w < 16; w++) {
            const int r = row0 + w * 8;
            float4 v = *(const float4*)(Qg + (size_t)r * CH + col4);
            Qs[r * ATT_STRIDE + col4 + 0] = f2tf32(v.x * SCALE);
            Qs[r * ATT_STRIDE + col4 + 1] = f2tf32(v.y * SCALE);
            Qs[r * ATT_STRIDE + col4 + 2] = f2tf32(v.z * SCALE);
            Qs[r * ATT_STRIDE + col4 + 3] = f2tf32(v.w * SCALE);
        }
    }

    float acc[16][4];
#pragma unroll
    for (int j = 0; j < 16; j++)
#pragma unroll
        for (int q = 0; q < 4; q++) acc[j][q] = 0.0f;
    float m1 = -1e30f, m2 = -1e30f, l1 = 0.0f, l2 = 0.0f;

    const int qr = warp * 16 + gid;  // this thread's base q-row in tile

    for (int kt = 0; kt < 16; kt++) {
        // load K & V tiles
        {
            const int col4 = (tid & 31) * 4;
            const int row0 = tid >> 5;
            const float* Kt = Kg + (size_t)kt * 128 * CH;
            const float* Vt = Vg + (size_t)kt * 128 * CH;
#pragma unroll
            for (int w = 0; w < 16; w++) {
                const int r = row0 + w * 8;
                float4 vk = *(const float4*)(Kt + (size_t)r * CH + col4);
                Ks[r * ATT_STRIDE + col4 + 0] = f2tf32(vk.x);
                Ks[r * ATT_STRIDE + col4 + 1] = f2tf32(vk.y);
                Ks[r * ATT_STRIDE + col4 + 2] = f2tf32(vk.z);
                Ks[r * ATT_STRIDE + col4 + 3] = f2tf32(vk.w);
                float4 vv = *(const float4*)(Vt + (size_t)r * CH + col4);
                Vs[r * ATT_STRIDE + col4 + 0] = f2tf32(vv.x);
                Vs[r * ATT_STRIDE + col4 + 1] = f2tf32(vv.y);
                Vs[r * ATT_STRIDE + col4 + 2] = f2tf32(vv.z);
                Vs[r * ATT_STRIDE + col4 + 3] = f2tf32(vv.w);
            }
        }
        __syncthreads();

        // S = Q @ K^T  (16 q-rows per warp x 128 keys)
        float sc[16][4];
#pragma unroll
        for (int j = 0; j < 16; j++)
#pragma unroll
            for (int q = 0; q < 4; q++) sc[j][q] = 0.0f;

#pragma unroll
        for (int kk = 0; kk < 16; kk++) {
            uint32_t a[4];
            a[0] = Qs[qr * ATT_STRIDE + kk * 8 + t4];
            a[1] = Qs[(qr + 8) * ATT_STRIDE + kk * 8 + t4];
            a[2] = Qs[qr * ATT_STRIDE + kk * 8 + t4 + 4];
            a[3] = Qs[(qr + 8) * ATT_STRIDE + kk * 8 + t4 + 4];
#pragma unroll
            for (int j = 0; j < 16; j++) {
                uint32_t b[2];
                b[0] = Ks[(j * 8 + gid) * ATT_STRIDE + kk * 8 + t4];
                b[1] = Ks[(j * 8 + gid) * ATT_STRIDE + kk * 8 + t4 + 4];
                mma_tf32(sc[j], a, b);
            }
        }

        // online softmax (rows qr and qr+8)
        float rmax1 = -1e30f, rmax2 = -1e30f;
#pragma unroll
        for (int j = 0; j < 16; j++) {
            rmax1 = fmaxf(rmax1, fmaxf(sc[j][0], sc[j][1]));
            rmax2 = fmaxf(rmax2, fmaxf(sc[j][2], sc[j][3]));
        }
        rmax1 = fmaxf(rmax1, __shfl_xor_sync(0xffffffffu, rmax1, 1));
        rmax1 = fmaxf(rmax1, __shfl_xor_sync(0xffffffffu, rmax1, 2));
        rmax2 = fmaxf(rmax2, __shfl_xor_sync(0xffffffffu, rmax2, 1));
        rmax2 = fmaxf(rmax2, __shfl_xor_sync(0xffffffffu, rmax2, 2));

        const float mn1 = fmaxf(m1, rmax1);
        const float mn2 = fmaxf(m2, rmax2);
        const float al1 = __expf(m1 - mn1);
        const float al2 = __expf(m2 - mn2);
        m1 = mn1; m2 = mn2;

        float s1 = 0.0f, s2 = 0.0f;
#pragma unroll
        for (int j = 0; j < 16; j++) {
            sc[j][0] = __expf(sc[j][0] - mn1);
            sc[j][1] = __expf(sc[j][1] - mn1);
            sc[j][2] = __expf(sc[j][2] - mn2);
            sc[j][3] = __expf(sc[j][3] - mn2);
            s1 += sc[j][0] + sc[j][1];
            s2 += sc[j][2] + sc[j][3];
        }
        s1 += __shfl_xor_sync(0xffffffffu, s1, 1);
        s1 += __shfl_xor_sync(0xffffffffu, s1, 2);
        s2 += __shfl_xor_sync(0xffffffffu, s2, 1);
        s2 += __shfl_xor_sync(0xffffffffu, s2, 2);
        l1 = l1 * al1 + s1;
        l2 = l2 * al2 + s2;

#pragma unroll
        for (int j = 0; j < 16; j++) {
            acc[j][0] *= al1; acc[j][1] *= al1;
            acc[j][2] *= al2; acc[j][3] *= al2;
        }

        __syncthreads();  // all warps done reading Ks

        // write P over Ks
#pragma unroll
        for (int j = 0; j < 16; j++) {
            const int c = j * 8 + t4 * 2;
            Ks[qr * ATT_STRIDE + c]           = f2tf32(sc[j][0]);
            Ks[qr * ATT_STRIDE + c + 1]       = f2tf32(sc[j][1]);
            Ks[(qr + 8) * ATT_STRIDE + c]     = f2tf32(sc[j][2]);
            Ks[(qr + 8) * ATT_STRIDE + c + 1] = f2tf32(sc[j][3]);
        }
        __syncthreads();

        // ctx += P @ V
#pragma unroll
        for (int kk = 0; kk < 16; kk++) {
            uint32_t a[4];
            a[0] = Ks[qr * ATT_STRIDE + kk * 8 + t4];
            a[1] = Ks[(qr + 8) * ATT_STRIDE + kk * 8 + t4];
            a[2] = Ks[qr * ATT_STRIDE + kk * 8 + t4 + 4];
            a[3] = Ks[(qr + 8) * ATT_STRIDE + kk * 8 + t4 + 4];
#pragma unroll
            for (int j = 0; j < 16; j++) {
                uint32_t b[2];
                b[0] = Vs[(kk * 8 + t4) * ATT_STRIDE + j * 8 + gid];
                b[1] = Vs[(kk * 8 + t4 + 4) * ATT_STRIDE + j * 8 + gid];
                mma_tf32(acc[j], a, b);
            }
        }
        __syncthreads();  // before next K/V overwrite
    }

    const float inv1 = 1.0f / l1;
    const float inv2 = 1.0f / l2;
#pragma unroll
    for (int j = 0; j < 16; j++) {
        const int c = j * 8 + t4 * 2;
        Og[(size_t)qr * CH + c]           = acc[j][0] * inv1;
        Og[(size_t)qr * CH + c + 1]       = acc[j][1] * inv1;
        Og[(size_t)(qr + 8) * CH + c]     = acc[j][2] * inv2;
        Og[(size_t)(qr + 8) * CH + c + 1] = acc[j][3] * inv2;
    }
}

// ---------------- bias + residual + LayerNorm ----------------
__global__ __launch_bounds__(256) void ln_kernel(const float* __restrict__ P,
                                                 const float* __restrict__ X,
                                                 const float* __restrict__ bp,
                                                 const float* __restrict__ gamma,
                                                 const float* __restrict__ beta,
                                                 float* __restrict__ out) {
    const int row = blockIdx.x;
    const int tid = threadIdx.x;

    float4 pv = ((const float4*)(P + (size_t)row * DD))[tid];
    float4 xv = ((const float4*)(X + (size_t)row * DD))[tid];
    float4 bv = ((const float4*)bp)[tid];
    float4 v;
    v.x = pv.x + xv.x + bv.x;
    v.y = pv.y + xv.y + bv.y;
    v.z = pv.z + xv.z + bv.z;
    v.w = pv.w + xv.w + bv.w;

    float s  = v.x + v.y + v.z + v.w;
    float sq = v.x * v.x + v.y * v.y + v.z * v.z + v.w * v.w;
#pragma unroll
    for (int o = 16; o > 0; o >>= 1) {
        s  += __shfl_xor_sync(0xffffffffu, s, o);
        sq += __shfl_xor_sync(0xffffffffu, sq, o);
    }
    __shared__ float ss[8], ssq[8];
    const int warp = tid >> 5;
    if ((tid & 31) == 0) { ss[warp] = s; ssq[warp] = sq; }
    __syncthreads();
    if (tid == 0) {
        float ts = 0.0f, tq = 0.0f;
#pragma unroll
        for (int w = 0; w < 8; w++) { ts += ss[w]; tq += ssq[w]; }
        ss[0] = ts; ssq[0] = tq;
    }
    __syncthreads();
    const float mean = ss[0] * (1.0f / DD);
    const float var  = ssq[0] * (1.0f / DD) - mean * mean;
    const float rstd = rsqrtf(var + LN_EPS);

    float4 gv = ((const float4*)gamma)[tid];
    float4 bt = ((const float4*)beta)[tid];
    float4 o;
    o.x = (v.x - mean) * rstd * gv.x + bt.x;
    o.y = (v.y - mean) * rstd * gv.y + bt.y;
    o.z = (v.z - mean) * rstd * gv.z + bt.z;
    o.w = (v.w - mean) * rstd * gv.w + bt.w;
    ((float4*)(out + (size_t)row * DD))[tid] = o;
}

// ---------------- launch ----------------
extern "C" void kernel_launch(void* const* d_in, const int* in_sizes, int n_in,
                              void* d_out, int out_size) {
    const float* query = (const float*)d_in[0];
    const float* keys  = (const float*)d_in[1];
    const float* Wq    = (const float*)d_in[2];
    const float* Wk    = (const float*)d_in[3];
    const float* Wv    = (const float*)d_in[4];
    const float* Wp    = (const float*)d_in[5];
    const float* bp    = (const float*)d_in[6];
    const float* ln_g  = (const float*)d_in[7];
    const float* ln_b  = (const float*)d_in[8];
    float* out = (float*)d_out;

    float *pQ, *pK, *pV, *pC;
    cudaGetSymbolAddress((void**)&pQ, g_Q);
    cudaGetSymbolAddress((void**)&pK, g_K);
    cudaGetSymbolAddress((void**)&pV, g_V);
    cudaGetSymbolAddress((void**)&pC, g_ctx);

    cudaFuncSetAttribute(attn_kernel, cudaFuncAttributeMaxDynamicSharedMemorySize,
                         ATT_SMEM_BYTES);

    dim3 ggrid(DD / 128, MM / 128);  // (8, 128)
    gemm_xwT<<<ggrid, 256>>>(query, Wq, pQ);
    gemm_xwT<<<ggrid, 256>>>(keys,  Wk, pK);
    gemm_xwT<<<ggrid, 256>>>(keys,  Wv, pV);

    attn_kernel<<<dim3(SS / 128, GG), 256, ATT_SMEM_BYTES>>>(pQ, pK, pV, pC);

    gemm_xwT<<<ggrid, 256>>>(pC, Wp, pK);  // g_K reused as proj output

    ln_kernel<<<MM, 256>>>(pK, query, bp, ln_g, ln_b, out);
}

// round 4
// speedup vs baseline: 2.2227x; 2.2227x over previous
#include <cuda_runtime.h>
#include <cuda_bf16.h>
#include <cstdint>

// Problem constants
#define BB 8
#define SS 2048
#define DD 1024
#define HH 8
#define CH 128            // CHUNK = D/H
#define GG (BB*HH)        // 64 groups after raw-view reshape
#define MM (BB*SS)        // 16384 rows for projection GEMMs
#define SCALE 0.03125f    // 1024^-0.5
#define LN_EPS 1e-5f

// ---------------- scratch (device globals; allocation-free) ----------------
__device__ __nv_bfloat16 g_Qb[(size_t)MM * DD];
__device__ __nv_bfloat16 g_Kb[(size_t)MM * DD];
__device__ __nv_bfloat16 g_Vb[(size_t)MM * DD];
__device__ float         g_ctx[(size_t)MM * DD];
__device__ float         g_O[(size_t)MM * DD];

// ---------------- helpers ----------------
__device__ __forceinline__ uint32_t smem_u32(const void* p) {
    return (uint32_t)__cvta_generic_to_shared(p);
}

__device__ __forceinline__ void ldsm4(uint32_t addr, uint32_t& r0, uint32_t& r1,
                                      uint32_t& r2, uint32_t& r3) {
    asm volatile("ldmatrix.sync.aligned.m8n8.x4.shared.b16 {%0,%1,%2,%3}, [%4];"
                 : "=r"(r0), "=r"(r1), "=r"(r2), "=r"(r3) : "r"(addr));
}

__device__ __forceinline__ void ldsm4t(uint32_t addr, uint32_t& r0, uint32_t& r1,
                                       uint32_t& r2, uint32_t& r3) {
    asm volatile("ldmatrix.sync.aligned.m8n8.x4.trans.shared.b16 {%0,%1,%2,%3}, [%4];"
                 : "=r"(r0), "=r"(r1), "=r"(r2), "=r"(r3) : "r"(addr));
}

__device__ __forceinline__ void mma_bf16(float c[4], const uint32_t a[4],
                                         uint32_t b0, uint32_t b1) {
    asm volatile(
        "mma.sync.aligned.m16n8k16.row.col.f32.bf16.bf16.f32 "
        "{%0,%1,%2,%3}, {%4,%5,%6,%7}, {%8,%9}, {%0,%1,%2,%3};\n"
        : "+f"(c[0]), "+f"(c[1]), "+f"(c[2]), "+f"(c[3])
        : "r"(a[0]), "r"(a[1]), "r"(a[2]), "r"(a[3]), "r"(b0), "r"(b1));
}

__device__ __forceinline__ uint32_t packbf2(float x, float y) {
    __nv_bfloat162 v = __floats2bfloat162_rn(x, y);
    return *reinterpret_cast<uint32_t*>(&v);
}

__device__ __forceinline__ void cp16(uint32_t dst, const void* src) {
    asm volatile("cp.async.cg.shared.global [%0], [%1], 16;" :: "r"(dst), "l"(src));
}

__device__ __forceinline__ void store2(__nv_bfloat16* C, size_t idx, float x, float y) {
    *(__nv_bfloat162*)(C + idx) = __floats2bfloat162_rn(x, y);
}
__device__ __forceinline__ void store2(float* C, size_t idx, float x, float y) {
    *(float2*)(C + idx) = make_float2(x, y);
}

// ---------------- GEMM: C[M,N] = A[M,K] @ W[N,K]^T (fp32 in, bf16 compute) ----
// CTA tile 128x128, K-step 64. 8 warps (4m x 2n), warp tile 32x64.
#define GS 72   // smem row stride (bf16 units): 64 + 8 pad -> conflict-free ldmatrix

template <typename OutT>
__global__ __launch_bounds__(256) void gemm_bf16(const float* __restrict__ A,
                                                 const float* __restrict__ W,
                                                 OutT* __restrict__ C) {
    __shared__ __nv_bfloat16 As[128 * GS];
    __shared__ __nv_bfloat16 Ws[128 * GS];

    const int tid  = threadIdx.x;
    const int warp = tid >> 5;
    const int lane = tid & 31;
    const int gid  = lane >> 2;
    const int t4   = lane & 3;
    const int wm   = warp & 3;
    const int wn   = warp >> 2;

    const int mBase = blockIdx.y * 128;
    const int nBase = blockIdx.x * 128;

    float acc[2][8][4];
#pragma unroll
    for (int mi = 0; mi < 2; mi++)
#pragma unroll
        for (int nj = 0; nj < 8; nj++)
#pragma unroll
            for (int q = 0; q < 4; q++) acc[mi][nj][q] = 0.0f;

    const int c4 = (tid & 15) * 4;   // k offset within block (floats)
    const int r0 = tid >> 4;         // 0..15
    const uint32_t AsB = smem_u32(As);
    const uint32_t WsB = smem_u32(Ws);

    for (int kb = 0; kb < DD; kb += 64) {
        float4 av[8], wv[8];
#pragma unroll
        for (int i = 0; i < 8; i++) {
            const int r = r0 + i * 16;
            av[i] = *(const float4*)(A + (size_t)(mBase + r) * DD + kb + c4);
            wv[i] = *(const float4*)(W + (size_t)(nBase + r) * DD + kb + c4);
        }
        __syncthreads();
#pragma unroll
        for (int i = 0; i < 8; i++) {
            const int r = r0 + i * 16;
            uint2 pa = make_uint2(packbf2(av[i].x, av[i].y), packbf2(av[i].z, av[i].w));
            uint2 pw = make_uint2(packbf2(wv[i].x, wv[i].y), packbf2(wv[i].z, wv[i].w));
            *(uint2*)(As + r * GS + c4) = pa;
            *(uint2*)(Ws + r * GS + c4) = pw;
        }
        __syncthreads();

#pragma unroll
        for (int ks = 0; ks < 4; ks++) {
            uint32_t af[2][4];
#pragma unroll
            for (int mi = 0; mi < 2; mi++) {
                uint32_t a = AsB + ((wm * 32 + mi * 16 + (lane & 15)) * GS +
                                    ((lane >> 4) & 1) * 8 + ks * 16) * 2;
                ldsm4(a, af[mi][0], af[mi][1], af[mi][2], af[mi][3]);
            }
#pragma unroll
            for (int j = 0; j < 4; j++) {
                uint32_t b0, b1, b2, b3;
                uint32_t a = WsB + ((wn * 64 + j * 16 + (lane & 7) + (lane >> 4) * 8) * GS +
                                    ((lane >> 3) & 1) * 8 + ks * 16) * 2;
                ldsm4(a, b0, b1, b2, b3);
#pragma unroll
                for (int mi = 0; mi < 2; mi++) {
                    mma_bf16(acc[mi][2 * j],     af[mi], b0, b1);
                    mma_bf16(acc[mi][2 * j + 1], af[mi], b2, b3);
                }
            }
        }
        __syncthreads();
    }

#pragma unroll
    for (int mi = 0; mi < 2; mi++) {
        const int r = mBase + wm * 32 + mi * 16 + gid;
#pragma unroll
        for (int nj = 0; nj < 8; nj++) {
            const int c = nBase + wn * 64 + nj * 8 + 2 * t4;
            store2(C, (size_t)r * DD + c,       acc[mi][nj][0], acc[mi][nj][1]);
            store2(C, (size_t)(r + 8) * DD + c, acc[mi][nj][2], acc[mi][nj][3]);
        }
    }
}

// ---------------- Flash attention (bf16, ldmatrix, cp.async double buffer) ----
// Grid (16 q-tiles, 64 groups), 256 threads (8 warps x 16 q-rows).
#define SKV 136                       // smem stride (bf16): 128 + 8 pad
#define TSZ (128 * SKV)               // one tile in bf16 elems
#define ATT_SMEM_BYTES (5 * TSZ * 2)  // Qs + 2xKs + 2xVs

__global__ void __launch_bounds__(256, 1)
attn_kernel(const __nv_bfloat16* __restrict__ Q, const __nv_bfloat16* __restrict__ K,
            const __nv_bfloat16* __restrict__ V, float* __restrict__ O) {
    extern __shared__ __nv_bfloat16 smb[];
    __nv_bfloat16* Qs = smb;
    __nv_bfloat16* KsA[2] = {smb + TSZ, smb + 2 * TSZ};
    __nv_bfloat16* VsA[2] = {smb + 3 * TSZ, smb + 4 * TSZ};

    const int tid  = threadIdx.x;
    const int warp = tid >> 5;
    const int lane = tid & 31;
    const int gid  = lane >> 2;
    const int t4   = lane & 3;

    const int g  = blockIdx.y;
    const int qt = blockIdx.x;

    const __nv_bfloat16* Qg = Q + (size_t)g * SS * CH + (size_t)qt * 128 * CH;
    const __nv_bfloat16* Kg = K + (size_t)g * SS * CH;
    const __nv_bfloat16* Vg = V + (size_t)g * SS * CH;
    float*               Og = O + (size_t)g * SS * CH + (size_t)qt * 128 * CH;

    const int col8 = (tid & 15) * 8;
    const int r0   = tid >> 4;

    // Q tile: plain load + store
#pragma unroll
    for (int i = 0; i < 8; i++) {
        const int r = r0 + i * 16;
        *(uint4*)(Qs + r * SKV + col8) = *(const uint4*)(Qg + (size_t)r * CH + col8);
    }

    // prefetch K/V tile 0
    {
        const __nv_bfloat16* Kt = Kg;
        const __nv_bfloat16* Vt = Vg;
#pragma unroll
        for (int i = 0; i < 8; i++) {
            const int r = r0 + i * 16;
            cp16(smem_u32(KsA[0] + r * SKV + col8), Kt + (size_t)r * CH + col8);
            cp16(smem_u32(VsA[0] + r * SKV + col8), Vt + (size_t)r * CH + col8);
        }
        asm volatile("cp.async.commit_group;");
    }
    __syncthreads();  // Q tile visible

    // preload Q fragments (8 k-steps x 4 regs)
    uint32_t qf[8][4];
#pragma unroll
    for (int ks = 0; ks < 8; ks++) {
        uint32_t a = smem_u32(Qs) + ((warp * 16 + (lane & 15)) * SKV +
                                     ((lane >> 4) & 1) * 8 + ks * 16) * 2;
        ldsm4(a, qf[ks][0], qf[ks][1], qf[ks][2], qf[ks][3]);
    }

    float oc[16][4];
#pragma unroll
    for (int j = 0; j < 16; j++)
#pragma unroll
        for (int q = 0; q < 4; q++) oc[j][q] = 0.0f;
    float m1 = -1e30f, m2 = -1e30f, l1 = 0.0f, l2 = 0.0f;

    for (int kt = 0; kt < 16; kt++) {
        if (kt < 15) {
            const __nv_bfloat16* Kt = Kg + (size_t)(kt + 1) * 128 * CH;
            const __nv_bfloat16* Vt = Vg + (size_t)(kt + 1) * 128 * CH;
            __nv_bfloat16* Kd = KsA[(kt + 1) & 1];
            __nv_bfloat16* Vd = VsA[(kt + 1) & 1];
#pragma unroll
            for (int i = 0; i < 8; i++) {
                const int r = r0 + i * 16;
                cp16(smem_u32(Kd + r * SKV + col8), Kt + (size_t)r * CH + col8);
                cp16(smem_u32(Vd + r * SKV + col8), Vt + (size_t)r * CH + col8);
            }
            asm volatile("cp.async.commit_group;");
            asm volatile("cp.async.wait_group 1;");
        } else {
            asm volatile("cp.async.wait_group 0;");
        }
        __syncthreads();

        const uint32_t Kbase = smem_u32(KsA[kt & 1]);
        const uint32_t Vbase = smem_u32(VsA[kt & 1]);

        // ---- S = Q @ K^T ----
        float sc[16][4];
#pragma unroll
        for (int j = 0; j < 16; j++)
#pragma unroll
            for (int q = 0; q < 4; q++) sc[j][q] = 0.0f;

#pragma unroll
        for (int ks = 0; ks < 8; ks++) {
#pragma unroll
            for (int j = 0; j < 8; j++) {
                uint32_t b0, b1, b2, b3;
                uint32_t a = Kbase + ((j * 16 + (lane & 7) + (lane >> 4) * 8) * SKV +
                                      ((lane >> 3) & 1) * 8 + ks * 16) * 2;
                ldsm4(a, b0, b1, b2, b3);
                mma_bf16(sc[2 * j],     qf[ks], b0, b1);
                mma_bf16(sc[2 * j + 1], qf[ks], b2, b3);
            }
        }

        // ---- online softmax (rows qr = warp*16+gid and +8) ----
        float rmax1 = -1e30f, rmax2 = -1e30f;
#pragma unroll
        for (int j = 0; j < 16; j++) {
            sc[j][0] *= SCALE; sc[j][1] *= SCALE; sc[j][2] *= SCALE; sc[j][3] *= SCALE;
            rmax1 = fmaxf(rmax1, fmaxf(sc[j][0], sc[j][1]));
            rmax2 = fmaxf(rmax2, fmaxf(sc[j][2], sc[j][3]));
        }
        rmax1 = fmaxf(rmax1, __shfl_xor_sync(0xffffffffu, rmax1, 1));
        rmax1 = fmaxf(rmax1, __shfl_xor_sync(0xffffffffu, rmax1, 2));
        rmax2 = fmaxf(rmax2, __shfl_xor_sync(0xffffffffu, rmax2, 1));
        rmax2 = fmaxf(rmax2, __shfl_xor_sync(0xffffffffu, rmax2, 2));

        const float mn1 = fmaxf(m1, rmax1);
        const float mn2 = fmaxf(m2, rmax2);
        const float al1 = __expf(m1 - mn1);
        const float al2 = __expf(m2 - mn2);
        m1 = mn1; m2 = mn2;

        float s1 = 0.0f, s2 = 0.0f;
#pragma unroll
        for (int j = 0; j < 16; j++) {
            sc[j][0] = __expf(sc[j][0] - mn1);
            sc[j][1] = __expf(sc[j][1] - mn1);
            sc[j][2] = __expf(sc[j][2] - mn2);
            sc[j][3] = __expf(sc[j][3] - mn2);
            s1 += sc[j][0] + sc[j][1];
            s2 += sc[j][2] + sc[j][3];
        }
        s1 += __shfl_xor_sync(0xffffffffu, s1, 1);
        s1 += __shfl_xor_sync(0xffffffffu, s1, 2);
        s2 += __shfl_xor_sync(0xffffffffu, s2, 1);
        s2 += __shfl_xor_sync(0xffffffffu, s2, 2);
        l1 = l1 * al1 + s1;
        l2 = l2 * al2 + s2;

#pragma unroll
        for (int j = 0; j < 16; j++) {
            oc[j][0] *= al1; oc[j][1] *= al1;
            oc[j][2] *= al2; oc[j][3] *= al2;
        }

        // ---- P (registers, bf16) : A-fragments for P@V directly from S accs ----
        uint32_t pf[8][4];
#pragma unroll
        for (int kk = 0; kk < 8; kk++) {
            pf[kk][0] = packbf2(sc[2 * kk][0],     sc[2 * kk][1]);
            pf[kk][1] = packbf2(sc[2 * kk][2],     sc[2 * kk][3]);
            pf[kk][2] = packbf2(sc[2 * kk + 1][0], sc[2 * kk + 1][1]);
            pf[kk][3] = packbf2(sc[2 * kk + 1][2], sc[2 * kk + 1][3]);
        }

        // ---- O += P @ V ----
#pragma unroll
        for (int kk = 0; kk < 8; kk++) {
#pragma unroll
            for (int j = 0; j < 8; j++) {
                uint32_t b0, b1, b2, b3;
                uint32_t a = Vbase + ((kk * 16 + (lane & 7) + ((lane >> 3) & 1) * 8) * SKV +
                                      j * 16 + (lane >> 4) * 8) * 2;
                ldsm4t(a, b0, b1, b2, b3);
                mma_bf16(oc[2 * j],     pf[kk], b0, b1);
                mma_bf16(oc[2 * j + 1], pf[kk], b2, b3);
            }
        }
        __syncthreads();  // done reading this buffer before next prefetch overwrites
    }

    const float inv1 = 1.0f / l1;
    const float inv2 = 1.0f / l2;
    const int qr = warp * 16 + gid;
#pragma unroll
    for (int j = 0; j < 16; j++) {
        const int c = j * 8 + 2 * t4;
        *(float2*)(Og + (size_t)qr * CH + c)       = make_float2(oc[j][0] * inv1, oc[j][1] * inv1);
        *(float2*)(Og + (size_t)(qr + 8) * CH + c) = make_float2(oc[j][2] * inv2, oc[j][3] * inv2);
    }
}

// ---------------- bias + residual + LayerNorm ----------------
__global__ __launch_bounds__(256) void ln_kernel(const float* __restrict__ P,
                                                 const float* __restrict__ X,
                                                 const float* __restrict__ bp,
                                                 const float* __restrict__ gamma,
                                                 const float* __restrict__ beta,
                                                 float* __restrict__ out) {
    const int row = blockIdx.x;
    const int tid = threadIdx.x;

    float4 pv = ((const float4*)(P + (size_t)row * DD))[tid];
    float4 xv = ((const float4*)(X + (size_t)row * DD))[tid];
    float4 bv = ((const float4*)bp)[tid];
    float4 v;
    v.x = pv.x + xv.x + bv.x;
    v.y = pv.y + xv.y + bv.y;
    v.z = pv.z + xv.z + bv.z;
    v.w = pv.w + xv.w + bv.w;

    float s  = v.x + v.y + v.z + v.w;
    float sq = v.x * v.x + v.y * v.y + v.z * v.z + v.w * v.w;
#pragma unroll
    for (int o = 16; o > 0; o >>= 1) {
        s  += __shfl_xor_sync(0xffffffffu, s, o);
        sq += __shfl_xor_sync(0xffffffffu, sq, o);
    }
    __shared__ float ss[8], ssq[8];
    const int warp = tid >> 5;
    if ((tid & 31) == 0) { ss[warp] = s; ssq[warp] = sq; }
    __syncthreads();
    if (tid == 0) {
        float ts = 0.0f, tq = 0.0f;
#pragma unroll
        for (int w = 0; w < 8; w++) { ts += ss[w]; tq += ssq[w]; }
        ss[0] = ts; ssq[0] = tq;
    }
    __syncthreads();
    const float mean = ss[0] * (1.0f / DD);
    const float var  = ssq[0] * (1.0f / DD) - mean * mean;
    const float rstd = rsqrtf(var + LN_EPS);

    float4 gv = ((const float4*)gamma)[tid];
    float4 bt = ((const float4*)beta)[tid];
    float4 o;
    o.x = (v.x - mean) * rstd * gv.x + bt.x;
    o.y = (v.y - mean) * rstd * gv.y + bt.y;
    o.z = (v.z - mean) * rstd * gv.z + bt.z;
    o.w = (v.w - mean) * rstd * gv.w + bt.w;
    ((float4*)(out + (size_t)row * DD))[tid] = o;
}

// ---------------- launch ----------------
extern "C" void kernel_launch(void* const* d_in, const int* in_sizes, int n_in,
                              void* d_out, int out_size) {
    const float* query = (const float*)d_in[0];
    const float* keys  = (const float*)d_in[1];
    const float* Wq    = (const float*)d_in[2];
    const float* Wk    = (const float*)d_in[3];
    const float* Wv    = (const float*)d_in[4];
    const float* Wp    = (const float*)d_in[5];
    const float* bp    = (const float*)d_in[6];
    const float* ln_g  = (const float*)d_in[7];
    const float* ln_b  = (const float*)d_in[8];
    float* out = (float*)d_out;

    __nv_bfloat16 *pQ, *pK, *pV;
    float *pC, *pO;
    cudaGetSymbolAddress((void**)&pQ, g_Qb);
    cudaGetSymbolAddress((void**)&pK, g_Kb);
    cudaGetSymbolAddress((void**)&pV, g_Vb);
    cudaGetSymbolAddress((void**)&pC, g_ctx);
    cudaGetSymbolAddress((void**)&pO, g_O);

    cudaFuncSetAttribute(attn_kernel, cudaFuncAttributeMaxDynamicSharedMemorySize,
                         ATT_SMEM_BYTES);

    dim3 ggrid(DD / 128, MM / 128);  // (8, 128)
    gemm_bf16<__nv_bfloat16><<<ggrid, 256>>>(query, Wq, pQ);
    gemm_bf16<__nv_bfloat16><<<ggrid, 256>>>(keys,  Wk, pK);
    gemm_bf16<__nv_bfloat16><<<ggrid, 256>>>(keys,  Wv, pV);

    attn_kernel<<<dim3(SS / 128, GG), 256, ATT_SMEM_BYTES>>>(pQ, pK, pV, pC);

    gemm_bf16<float><<<ggrid, 256>>>(pC, Wp, pO);

    ln_kernel<<<MM, 256>>>(pO, query, bp, ln_g, ln_b, out);
}

// round 6
// speedup vs baseline: 3.5347x; 1.5903x over previous
#include <cuda_runtime.h>
#include <cuda_bf16.h>
#include <cstdint>

// Problem constants
#define BB 8
#define SS 2048
#define DD 1024
#define HH 8
#define CH 128
#define GG (BB*HH)
#define MM (BB*SS)
#define SCALE 0.03125f
#define LN_EPS 1e-5f

// ---------------- scratch (device globals; allocation-free) ----------------
__device__ __nv_bfloat16 g_Aq[(size_t)MM * DD];   // query bf16
__device__ __nv_bfloat16 g_Ak[(size_t)MM * DD];   // keys bf16
__device__ __nv_bfloat16 g_Wqb[DD * DD];
__device__ __nv_bfloat16 g_Wkb[DD * DD];
__device__ __nv_bfloat16 g_Wvb[DD * DD];
__device__ __nv_bfloat16 g_Wpb[DD * DD];
__device__ __nv_bfloat16 g_Qb[(size_t)MM * DD];
__device__ __nv_bfloat16 g_Kb[(size_t)MM * DD];
__device__ __nv_bfloat16 g_Vb[(size_t)MM * DD];
__device__ __nv_bfloat16 g_Cb[(size_t)MM * DD];   // attention ctx bf16
__device__ float         g_O[(size_t)MM * DD];

// ---------------- helpers ----------------
__device__ __forceinline__ uint32_t smem_u32(const void* p) {
    return (uint32_t)__cvta_generic_to_shared(p);
}
__device__ __forceinline__ uint32_t packbf2(float x, float y) {
    __nv_bfloat162 v = __floats2bfloat162_rn(x, y);
    return *reinterpret_cast<uint32_t*>(&v);
}
__device__ __forceinline__ void cp16(uint32_t dst, const void* src) {
    asm volatile("cp.async.cg.shared.global [%0], [%1], 16;" :: "r"(dst), "l"(src));
}
__device__ __forceinline__ void ldsm4(uint32_t addr, uint32_t& r0, uint32_t& r1,
                                      uint32_t& r2, uint32_t& r3) {
    asm volatile("ldmatrix.sync.aligned.m8n8.x4.shared.b16 {%0,%1,%2,%3}, [%4];"
                 : "=r"(r0), "=r"(r1), "=r"(r2), "=r"(r3) : "r"(addr));
}
__device__ __forceinline__ void ldsm4t(uint32_t addr, uint32_t& r0, uint32_t& r1,
                                       uint32_t& r2, uint32_t& r3) {
    asm volatile("ldmatrix.sync.aligned.m8n8.x4.trans.shared.b16 {%0,%1,%2,%3}, [%4];"
                 : "=r"(r0), "=r"(r1), "=r"(r2), "=r"(r3) : "r"(addr));
}
__device__ __forceinline__ void mma_bf16(float c[4], const uint32_t a[4],
                                         uint32_t b0, uint32_t b1) {
    asm volatile(
        "mma.sync.aligned.m16n8k16.row.col.f32.bf16.bf16.f32 "
        "{%0,%1,%2,%3}, {%4,%5,%6,%7}, {%8,%9}, {%0,%1,%2,%3};\n"
        : "+f"(c[0]), "+f"(c[1]), "+f"(c[2]), "+f"(c[3])
        : "r"(a[0]), "r"(a[1]), "r"(a[2]), "r"(a[3]), "r"(b0), "r"(b1));
}
__device__ __forceinline__ void store2(__nv_bfloat16* C, size_t idx, float x, float y) {
    *(__nv_bfloat162*)(C + idx) = __floats2bfloat162_rn(x, y);
}
__device__ __forceinline__ void store2(float* C, size_t idx, float x, float y) {
    *(float2*)(C + idx) = make_float2(x, y);
}

// ---------------- fp32 -> bf16 conversion ----------------
__global__ __launch_bounds__(256) void f2bf_kernel(const float4* __restrict__ in,
                                                   uint2* __restrict__ out, int n4) {
    int i = blockIdx.x * blockDim.x + threadIdx.x;
    if (i < n4) {
        float4 v = in[i];
        out[i] = make_uint2(packbf2(v.x, v.y), packbf2(v.z, v.w));
    }
}

// ---------------- pipelined bf16 GEMM: C[M,N] = A[M,K] @ W[N,K]^T ----------
// CTA tile 128x128, k-step 64, 2-stage cp.async double buffer.
// 8 warps (4m x 2n), warp tile 32x64.
#define GS 72                               // smem row stride (bf16): 64 + 8 pad
#define GST (128 * GS)                      // one matrix stage (elems)
#define GEMM_SMEM_BYTES (4 * GST * 2)       // 2 stages x (A + W)

template <typename OutT>
__global__ __launch_bounds__(256) void gemm_pl(const __nv_bfloat16* __restrict__ A,
                                               const __nv_bfloat16* __restrict__ W,
                                               OutT* __restrict__ C) {
    extern __shared__ __nv_bfloat16 gsm[];
    __nv_bfloat16* AsB[2] = {gsm,           gsm + 2 * GST};
    __nv_bfloat16* WsB[2] = {gsm + GST,     gsm + 3 * GST};

    const int tid  = threadIdx.x;
    const int warp = tid >> 5;
    const int lane = tid & 31;
    const int gid  = lane >> 2;
    const int t4   = lane & 3;
    const int wm   = warp & 3;
    const int wn   = warp >> 2;

    const int mBase = blockIdx.y * 128;
    const int nBase = blockIdx.x * 128;

    float acc[2][8][4];
#pragma unroll
    for (int mi = 0; mi < 2; mi++)
#pragma unroll
        for (int nj = 0; nj < 8; nj++)
#pragma unroll
            for (int q = 0; q < 4; q++) acc[mi][nj][q] = 0.0f;

    const int lr = tid >> 3;   // 0..31 row base
    const int lg = tid & 7;    // 16B chunk within 64-col stage

    // prologue: stage 0
    {
        __nv_bfloat16* dA = AsB[0];
        __nv_bfloat16* dW = WsB[0];
#pragma unroll
        for (int i = 0; i < 4; i++) {
            const int r = lr + i * 32;
            cp16(smem_u32(dA + r * GS + lg * 8), A + (size_t)(mBase + r) * DD + lg * 8);
            cp16(smem_u32(dW + r * GS + lg * 8), W + (size_t)(nBase + r) * DD + lg * 8);
        }
        asm volatile("cp.async.commit_group;");
    }

    for (int s = 0; s < 16; s++) {
        if (s < 15) {
            const int kb = (s + 1) * 64;
            __nv_bfloat16* dA = AsB[(s + 1) & 1];
            __nv_bfloat16* dW = WsB[(s + 1) & 1];
#pragma unroll
            for (int i = 0; i < 4; i++) {
                const int r = lr + i * 32;
                cp16(smem_u32(dA + r * GS + lg * 8), A + (size_t)(mBase + r) * DD + kb + lg * 8);
                cp16(smem_u32(dW + r * GS + lg * 8), W + (size_t)(nBase + r) * DD + kb + lg * 8);
            }
            asm volatile("cp.async.commit_group;");
            asm volatile("cp.async.wait_group 1;");
        } else {
            asm volatile("cp.async.wait_group 0;");
        }
        __syncthreads();

        const uint32_t AsA = smem_u32(AsB[s & 1]);
        const uint32_t WsA = smem_u32(WsB[s & 1]);

#pragma unroll
        for (int ks = 0; ks < 4; ks++) {
            uint32_t af[2][4];
#pragma unroll
            for (int mi = 0; mi < 2; mi++) {
                uint32_t a = AsA + ((wm * 32 + mi * 16 + (lane & 15)) * GS +
                                    ((lane >> 4) & 1) * 8 + ks * 16) * 2;
                ldsm4(a, af[mi][0], af[mi][1], af[mi][2], af[mi][3]);
            }
#pragma unroll
            for (int j = 0; j < 4; j++) {
                uint32_t b0, b1, b2, b3;
                uint32_t a = WsA + ((wn * 64 + j * 16 + (lane & 7) + (lane >> 4) * 8) * GS +
                                    ((lane >> 3) & 1) * 8 + ks * 16) * 2;
                ldsm4(a, b0, b1, b2, b3);
#pragma unroll
                for (int mi = 0; mi < 2; mi++) {
                    mma_bf16(acc[mi][2 * j],     af[mi], b0, b1);
                    mma_bf16(acc[mi][2 * j + 1], af[mi], b2, b3);
                }
            }
        }
        __syncthreads();
    }

#pragma unroll
    for (int mi = 0; mi < 2; mi++) {
        const int r = mBase + wm * 32 + mi * 16 + gid;
#pragma unroll
        for (int nj = 0; nj < 8; nj++) {
            const int c = nBase + wn * 64 + nj * 8 + 2 * t4;
            store2(C, (size_t)r * DD + c,       acc[mi][nj][0], acc[mi][nj][1]);
            store2(C, (size_t)(r + 8) * DD + c, acc[mi][nj][2], acc[mi][nj][3]);
        }
    }
}

// ---------------- Flash attention (bf16, ldmatrix, cp.async double buffer) ----
#define SKV 136
#define TSZ (128 * SKV)
#define ATT_SMEM_BYTES (5 * TSZ * 2)

__global__ void __launch_bounds__(256, 1)
attn_kernel(const __nv_bfloat16* __restrict__ Q, const __nv_bfloat16* __restrict__ K,
            const __nv_bfloat16* __restrict__ V, __nv_bfloat16* __restrict__ O) {
    extern __shared__ __nv_bfloat16 smb[];
    __nv_bfloat16* Qs = smb;
    __nv_bfloat16* KsA[2] = {smb + TSZ, smb + 2 * TSZ};
    __nv_bfloat16* VsA[2] = {smb + 3 * TSZ, smb + 4 * TSZ};

    const int tid  = threadIdx.x;
    const int warp = tid >> 5;
    const int lane = tid & 31;
    const int gid  = lane >> 2;
    const int t4   = lane & 3;

    const int g  = blockIdx.y;
    const int qt = blockIdx.x;

    const __nv_bfloat16* Qg = Q + (size_t)g * SS * CH + (size_t)qt * 128 * CH;
    const __nv_bfloat16* Kg = K + (size_t)g * SS * CH;
    const __nv_bfloat16* Vg = V + (size_t)g * SS * CH;
    __nv_bfloat16*       Og = O + (size_t)g * SS * CH + (size_t)qt * 128 * CH;

    const int col8 = (tid & 15) * 8;
    const int r0   = tid >> 4;

#pragma unroll
    for (int i = 0; i < 8; i++) {
        const int r = r0 + i * 16;
        *(uint4*)(Qs + r * SKV + col8) = *(const uint4*)(Qg + (size_t)r * CH + col8);
    }

    {
#pragma unroll
        for (int i = 0; i < 8; i++) {
            const int r = r0 + i * 16;
            cp16(smem_u32(KsA[0] + r * SKV + col8), Kg + (size_t)r * CH + col8);
            cp16(smem_u32(VsA[0] + r * SKV + col8), Vg + (size_t)r * CH + col8);
        }
        asm volatile("cp.async.commit_group;");
    }
    __syncthreads();

    uint32_t qf[8][4];
#pragma unroll
    for (int ks = 0; ks < 8; ks++) {
        uint32_t a = smem_u32(Qs) + ((warp * 16 + (lane & 15)) * SKV +
                                     ((lane >> 4) & 1) * 8 + ks * 16) * 2;
        ldsm4(a, qf[ks][0], qf[ks][1], qf[ks][2], qf[ks][3]);
    }

    float oc[16][4];
#pragma unroll
    for (int j = 0; j < 16; j++)
#pragma unroll
        for (int q = 0; q < 4; q++) oc[j][q] = 0.0f;
    float m1 = -1e30f, m2 = -1e30f, l1 = 0.0f, l2 = 0.0f;

    for (int kt = 0; kt < 16; kt++) {
        if (kt < 15) {
            const __nv_bfloat16* Kt = Kg + (size_t)(kt + 1) * 128 * CH;
            const __nv_bfloat16* Vt = Vg + (size_t)(kt + 1) * 128 * CH;
            __nv_bfloat16* Kd = KsA[(kt + 1) & 1];
            __nv_bfloat16* Vd = VsA[(kt + 1) & 1];
#pragma unroll
            for (int i = 0; i < 8; i++) {
                const int r = r0 + i * 16;
                cp16(smem_u32(Kd + r * SKV + col8), Kt + (size_t)r * CH + col8);
                cp16(smem_u32(Vd + r * SKV + col8), Vt + (size_t)r * CH + col8);
            }
            asm volatile("cp.async.commit_group;");
            asm volatile("cp.async.wait_group 1;");
        } else {
            asm volatile("cp.async.wait_group 0;");
        }
        __syncthreads();

        const uint32_t Kbase = smem_u32(KsA[kt & 1]);
        const uint32_t Vbase = smem_u32(VsA[kt & 1]);

        float sc[16][4];
#pragma unroll
        for (int j = 0; j < 16; j++)
#pragma unroll
            for (int q = 0; q < 4; q++) sc[j][q] = 0.0f;

#pragma unroll
        for (int ks = 0; ks < 8; ks++) {
#pragma unroll
            for (int j = 0; j < 8; j++) {
                uint32_t b0, b1, b2, b3;
                uint32_t a = Kbase + ((j * 16 + (lane & 7) + (lane >> 4) * 8) * SKV +
                                      ((lane >> 3) & 1) * 8 + ks * 16) * 2;
                ldsm4(a, b0, b1, b2, b3);
                mma_bf16(sc[2 * j],     qf[ks], b0, b1);
                mma_bf16(sc[2 * j + 1], qf[ks], b2, b3);
            }
        }

        float rmax1 = -1e30f, rmax2 = -1e30f;
#pragma unroll
        for (int j = 0; j < 16; j++) {
            sc[j][0] *= SCALE; sc[j][1] *= SCALE; sc[j][2] *= SCALE; sc[j][3] *= SCALE;
            rmax1 = fmaxf(rmax1, fmaxf(sc[j][0], sc[j][1]));
            rmax2 = fmaxf(rmax2, fmaxf(sc[j][2], sc[j][3]));
        }
        rmax1 = fmaxf(rmax1, __shfl_xor_sync(0xffffffffu, rmax1, 1));
        rmax1 = fmaxf(rmax1, __shfl_xor_sync(0xffffffffu, rmax1, 2));
        rmax2 = fmaxf(rmax2, __shfl_xor_sync(0xffffffffu, rmax2, 1));
        rmax2 = fmaxf(rmax2, __shfl_xor_sync(0xffffffffu, rmax2, 2));

        const float mn1 = fmaxf(m1, rmax1);
        const float mn2 = fmaxf(m2, rmax2);
        const float al1 = __expf(m1 - mn1);
        const float al2 = __expf(m2 - mn2);
        m1 = mn1; m2 = mn2;

        float s1 = 0.0f, s2 = 0.0f;
#pragma unroll
        for (int j = 0; j < 16; j++) {
            sc[j][0] = __expf(sc[j][0] - mn1);
            sc[j][1] = __expf(sc[j][1] - mn1);
            sc[j][2] = __expf(sc[j][2] - mn2);
            sc[j][3] = __expf(sc[j][3] - mn2);
            s1 += sc[j][0] + sc[j][1];
            s2 += sc[j][2] + sc[j][3];
        }
        s1 += __shfl_xor_sync(0xffffffffu, s1, 1);
        s1 += __shfl_xor_sync(0xffffffffu, s1, 2);
        s2 += __shfl_xor_sync(0xffffffffu, s2, 1);
        s2 += __shfl_xor_sync(0xffffffffu, s2, 2);
        l1 = l1 * al1 + s1;
        l2 = l2 * al2 + s2;

#pragma unroll
        for (int j = 0; j < 16; j++) {
            oc[j][0] *= al1; oc[j][1] *= al1;
            oc[j][2] *= al2; oc[j][3] *= al2;
        }

        uint32_t pf[8][4];
#pragma unroll
        for (int kk = 0; kk < 8; kk++) {
            pf[kk][0] = packbf2(sc[2 * kk][0],     sc[2 * kk][1]);
            pf[kk][1] = packbf2(sc[2 * kk][2],     sc[2 * kk][3]);
            pf[kk][2] = packbf2(sc[2 * kk + 1][0], sc[2 * kk + 1][1]);
            pf[kk][3] = packbf2(sc[2 * kk + 1][2], sc[2 * kk + 1][3]);
        }

#pragma unroll
        for (int kk = 0; kk < 8; kk++) {
#pragma unroll
            for (int j = 0; j < 8; j++) {
                uint32_t b0, b1, b2, b3;
                uint32_t a = Vbase + ((kk * 16 + (lane & 7) + ((lane >> 3) & 1) * 8) * SKV +
                                      j * 16 + (lane >> 4) * 8) * 2;
                ldsm4t(a, b0, b1, b2, b3);
                mma_bf16(oc[2 * j],     pf[kk], b0, b1);
                mma_bf16(oc[2 * j + 1], pf[kk], b2, b3);
            }
        }
        __syncthreads();
    }

    const float inv1 = 1.0f / l1;
    const float inv2 = 1.0f / l2;
    const int qr = warp * 16 + gid;
#pragma unroll
    for (int j = 0; j < 16; j++) {
        const int c = j * 8 + 2 * t4;
        *(__nv_bfloat162*)(Og + (size_t)qr * CH + c) =
            __floats2bfloat162_rn(oc[j][0] * inv1, oc[j][1] * inv1);
        *(__nv_bfloat162*)(Og + (size_t)(qr + 8) * CH + c) =
            __floats2bfloat162_rn(oc[j][2] * inv2, oc[j][3] * inv2);
    }
}

// ---------------- bias + residual + LayerNorm ----------------
__global__ __launch_bounds__(256) void ln_kernel(const float* __restrict__ P,
                                                 const float* __restrict__ X,
                                                 const float* __restrict__ bp,
                                                 const float* __restrict__ gamma,
                                                 const float* __restrict__ beta,
                                                 float* __restrict__ out) {
    const int row = blockIdx.x;
    const int tid = threadIdx.x;

    float4 pv = ((const float4*)(P + (size_t)row * DD))[tid];
    float4 xv = ((const float4*)(X + (size_t)row * DD))[tid];
    float4 bv = ((const float4*)bp)[tid];
    float4 v;
    v.x = pv.x + xv.x + bv.x;
    v.y = pv.y + xv.y + bv.y;
    v.z = pv.z + xv.z + bv.z;
    v.w = pv.w + xv.w + bv.w;

    float s  = v.x + v.y + v.z + v.w;
    float sq = v.x * v.x + v.y * v.y + v.z * v.z + v.w * v.w;
#pragma unroll
    for (int o = 16; o > 0; o >>= 1) {
        s  += __shfl_xor_sync(0xffffffffu, s, o);
        sq += __shfl_xor_sync(0xffffffffu, sq, o);
    }
    __shared__ float ss[8], ssq[8];
    const int warp = tid >> 5;
    if ((tid & 31) == 0) { ss[warp] = s; ssq[warp] = sq; }
    __syncthreads();
    if (tid == 0) {
        float ts = 0.0f, tq = 0.0f;
#pragma unroll
        for (int w = 0; w < 8; w++) { ts += ss[w]; tq += ssq[w]; }
        ss[0] = ts; ssq[0] = tq;
    }
    __syncthreads();
    const float mean = ss[0] * (1.0f / DD);
    const float var  = ssq[0] * (1.0f / DD) - mean * mean;
    const float rstd = rsqrtf(var + LN_EPS);

    float4 gv = ((const float4*)gamma)[tid];
    float4 bt = ((const float4*)beta)[tid];
    float4 o;
    o.x = (v.x - mean) * rstd * gv.x + bt.x;
    o.y = (v.y - mean) * rstd * gv.y + bt.y;
    o.z = (v.z - mean) * rstd * gv.z + bt.z;
    o.w = (v.w - mean) * rstd * gv.w + bt.w;
    ((float4*)(out + (size_t)row * DD))[tid] = o;
}

// ---------------- launch ----------------
extern "C" void kernel_launch(void* const* d_in, const int* in_sizes, int n_in,
                              void* d_out, int out_size) {
    const float* query = (const float*)d_in[0];
    const float* keys  = (const float*)d_in[1];
    const float* Wq    = (const float*)d_in[2];
    const float* Wk    = (const float*)d_in[3];
    const float* Wv    = (const float*)d_in[4];
    const float* Wp    = (const float*)d_in[5];
    const float* bp    = (const float*)d_in[6];
    const float* ln_g  = (const float*)d_in[7];
    const float* ln_b  = (const float*)d_in[8];
    float* out = (float*)d_out;

    __nv_bfloat16 *pAq, *pAk, *pWq, *pWk, *pWv, *pWp, *pQ, *pK, *pV, *pC;
    float *pO;
    cudaGetSymbolAddress((void**)&pAq, g_Aq);
    cudaGetSymbolAddress((void**)&pAk, g_Ak);
    cudaGetSymbolAddress((void**)&pWq, g_Wqb);
    cudaGetSymbolAddress((void**)&pWk, g_Wkb);
    cudaGetSymbolAddress((void**)&pWv, g_Wvb);
    cudaGetSymbolAddress((void**)&pWp, g_Wpb);
    cudaGetSymbolAddress((void**)&pQ,  g_Qb);
    cudaGetSymbolAddress((void**)&pK,  g_Kb);
    cudaGetSymbolAddress((void**)&pV,  g_Vb);
    cudaGetSymbolAddress((void**)&pC,  g_Cb);
    cudaGetSymbolAddress((void**)&pO,  g_O);

    cudaFuncSetAttribute(attn_kernel, cudaFuncAttributeMaxDynamicSharedMemorySize,
                         ATT_SMEM_BYTES);
    cudaFuncSetAttribute(gemm_pl<__nv_bfloat16>, cudaFuncAttributeMaxDynamicSharedMemorySize,
                         GEMM_SMEM_BYTES);
    cudaFuncSetAttribute(gemm_pl<float>, cudaFuncAttributeMaxDynamicSharedMemorySize,
                         GEMM_SMEM_BYTES);

    // fp32 -> bf16 conversions (once; removes converts + halves traffic in GEMMs)
    const int n4a = (MM * DD) / 4;
    const int n4w = (DD * DD) / 4;
    f2bf_kernel<<<n4a / 256, 256>>>((const float4*)query, (uint2*)pAq, n4a);
    f2bf_kernel<<<n4a / 256, 256>>>((const float4*)keys,  (uint2*)pAk, n4a);
    f2bf_kernel<<<n4w / 256, 256>>>((const float4*)Wq, (uint2*)pWq, n4w);
    f2bf_kernel<<<n4w / 256, 256>>>((const float4*)Wk, (uint2*)pWk, n4w);
    f2bf_kernel<<<n4w / 256, 256>>>((const float4*)Wv, (uint2*)pWv, n4w);
    f2bf_kernel<<<n4w / 256, 256>>>((const float4*)Wp, (uint2*)pWp, n4w);

    dim3 ggrid(DD / 128, MM / 128);  // (8, 128)
    gemm_pl<__nv_bfloat16><<<ggrid, 256, GEMM_SMEM_BYTES>>>(pAq, pWq, pQ);
    gemm_pl<__nv_bfloat16><<<ggrid, 256, GEMM_SMEM_BYTES>>>(pAk, pWk, pK);
    gemm_pl<__nv_bfloat16><<<ggrid, 256, GEMM_SMEM_BYTES>>>(pAk, pWv, pV);

    attn_kernel<<<dim3(SS / 128, GG), 256, ATT_SMEM_BYTES>>>(pQ, pK, pV, pC);

    gemm_pl<float><<<ggrid, 256, GEMM_SMEM_BYTES>>>(pC, pWp, pO);

    ln_kernel<<<MM, 256>>>(pO, query, bp, ln_g, ln_b, out);
}

// round 7
// speedup vs baseline: 3.6668x; 1.0374x over previous
#include <cuda_runtime.h>
#include <cuda_bf16.h>
#include <cstdint>

// Problem constants
#define BB 8
#define SS 2048
#define DD 1024
#define HH 8
#define CH 128
#define GG (BB*HH)
#define MM (BB*SS)
#define SCALE 0.03125f
#define LN_EPS 1e-5f

// ---------------- scratch (device globals; allocation-free) ----------------
__device__ __nv_bfloat16 g_Aq[(size_t)MM * DD];   // query bf16
__device__ __nv_bfloat16 g_Ak[(size_t)MM * DD];   // keys bf16
__device__ __nv_bfloat16 g_Wqb[DD * DD];
__device__ __nv_bfloat16 g_Wkb[DD * DD];
__device__ __nv_bfloat16 g_Wvb[DD * DD];
__device__ __nv_bfloat16 g_Wpb[DD * DD];
__device__ __nv_bfloat16 g_Qb[(size_t)MM * DD];
__device__ __nv_bfloat16 g_Kb[(size_t)MM * DD];
__device__ __nv_bfloat16 g_Vb[(size_t)MM * DD];
__device__ __nv_bfloat16 g_Cb[(size_t)MM * DD];   // attention ctx bf16
__device__ float         g_O[(size_t)MM * DD];

// ---------------- helpers ----------------
__device__ __forceinline__ uint32_t smem_u32(const void* p) {
    return (uint32_t)__cvta_generic_to_shared(p);
}
__device__ __forceinline__ uint32_t packbf2(float x, float y) {
    __nv_bfloat162 v = __floats2bfloat162_rn(x, y);
    return *reinterpret_cast<uint32_t*>(&v);
}
__device__ __forceinline__ void cp16(uint32_t dst, const void* src) {
    asm volatile("cp.async.cg.shared.global [%0], [%1], 16;" :: "r"(dst), "l"(src));
}
__device__ __forceinline__ void ldsm4(uint32_t addr, uint32_t& r0, uint32_t& r1,
                                      uint32_t& r2, uint32_t& r3) {
    asm volatile("ldmatrix.sync.aligned.m8n8.x4.shared.b16 {%0,%1,%2,%3}, [%4];"
                 : "=r"(r0), "=r"(r1), "=r"(r2), "=r"(r3) : "r"(addr));
}
__device__ __forceinline__ void ldsm4t(uint32_t addr, uint32_t& r0, uint32_t& r1,
                                       uint32_t& r2, uint32_t& r3) {
    asm volatile("ldmatrix.sync.aligned.m8n8.x4.trans.shared.b16 {%0,%1,%2,%3}, [%4];"
                 : "=r"(r0), "=r"(r1), "=r"(r2), "=r"(r3) : "r"(addr));
}
__device__ __forceinline__ void mma_bf16(float c[4], const uint32_t a[4],
                                         uint32_t b0, uint32_t b1) {
    asm volatile(
        "mma.sync.aligned.m16n8k16.row.col.f32.bf16.bf16.f32 "
        "{%0,%1,%2,%3}, {%4,%5,%6,%7}, {%8,%9}, {%0,%1,%2,%3};\n"
        : "+f"(c[0]), "+f"(c[1]), "+f"(c[2]), "+f"(c[3])
        : "r"(a[0]), "r"(a[1]), "r"(a[2]), "r"(a[3]), "r"(b0), "r"(b1));
}
__device__ __forceinline__ uint32_t mul_bf16x2(uint32_t a, uint32_t b) {
    uint32_t r;
    asm("mul.bf16x2 %0, %1, %2;" : "=r"(r) : "r"(a), "r"(b));
    return r;
}
__device__ __forceinline__ void store2(__nv_bfloat16* C, size_t idx, float x, float y) {
    *(__nv_bfloat162*)(C + idx) = __floats2bfloat162_rn(x, y);
}
__device__ __forceinline__ void store2(float* C, size_t idx, float x, float y) {
    *(float2*)(C + idx) = make_float2(x, y);
}

// ---------------- fp32 -> bf16 conversion ----------------
__global__ __launch_bounds__(256) void f2bf_kernel(const float4* __restrict__ in,
                                                   uint2* __restrict__ out, int n4) {
    int i = blockIdx.x * blockDim.x + threadIdx.x;
    if (i < n4) {
        float4 v = in[i];
        out[i] = make_uint2(packbf2(v.x, v.y), packbf2(v.z, v.w));
    }
}

// ---------------- pipelined bf16 GEMM: C[M,N] = A[M,K] @ W[N,K]^T ----------
// CTA tile 128x128, k-step 64, 2-stage cp.async double buffer, 2 CTAs/SM.
// 8 warps (4m x 2n), warp tile 32x64.
#define GS 72                               // smem row stride (bf16): 64 + 8 pad
#define GST (128 * GS)                      // one matrix stage (elems)
#define GEMM_SMEM_BYTES (4 * GST * 2)       // 2 stages x (A + W)

template <typename OutT>
__global__ __launch_bounds__(256, 2) void gemm_pl(const __nv_bfloat16* __restrict__ A,
                                                  const __nv_bfloat16* __restrict__ W,
                                                  OutT* __restrict__ C) {
    extern __shared__ __nv_bfloat16 gsm[];
    __nv_bfloat16* AsB[2] = {gsm,           gsm + 2 * GST};
    __nv_bfloat16* WsB[2] = {gsm + GST,     gsm + 3 * GST};

    const int tid  = threadIdx.x;
    const int warp = tid >> 5;
    const int lane = tid & 31;
    const int gid  = lane >> 2;
    const int t4   = lane & 3;
    const int wm   = warp & 3;
    const int wn   = warp >> 2;

    const int mBase = blockIdx.y * 128;
    const int nBase = blockIdx.x * 128;

    float acc[2][8][4];
#pragma unroll
    for (int mi = 0; mi < 2; mi++)
#pragma unroll
        for (int nj = 0; nj < 8; nj++)
#pragma unroll
            for (int q = 0; q < 4; q++) acc[mi][nj][q] = 0.0f;

    const int lr = tid >> 3;   // 0..31 row base
    const int lg = tid & 7;    // 16B chunk within 64-col stage

    // prologue: stage 0
    {
        __nv_bfloat16* dA = AsB[0];
        __nv_bfloat16* dW = WsB[0];
#pragma unroll
        for (int i = 0; i < 4; i++) {
            const int r = lr + i * 32;
            cp16(smem_u32(dA + r * GS + lg * 8), A + (size_t)(mBase + r) * DD + lg * 8);
            cp16(smem_u32(dW + r * GS + lg * 8), W + (size_t)(nBase + r) * DD + lg * 8);
        }
        asm volatile("cp.async.commit_group;");
    }

    for (int s = 0; s < 16; s++) {
        if (s < 15) {
            const int kb = (s + 1) * 64;
            __nv_bfloat16* dA = AsB[(s + 1) & 1];
            __nv_bfloat16* dW = WsB[(s + 1) & 1];
#pragma unroll
            for (int i = 0; i < 4; i++) {
                const int r = lr + i * 32;
                cp16(smem_u32(dA + r * GS + lg * 8), A + (size_t)(mBase + r) * DD + kb + lg * 8);
                cp16(smem_u32(dW + r * GS + lg * 8), W + (size_t)(nBase + r) * DD + kb + lg * 8);
            }
            asm volatile("cp.async.commit_group;");
            asm volatile("cp.async.wait_group 1;");
        } else {
            asm volatile("cp.async.wait_group 0;");
        }
        __syncthreads();

        const uint32_t AsA = smem_u32(AsB[s & 1]);
        const uint32_t WsA = smem_u32(WsB[s & 1]);

#pragma unroll
        for (int ks = 0; ks < 4; ks++) {
            uint32_t af[2][4];
#pragma unroll
            for (int mi = 0; mi < 2; mi++) {
                uint32_t a = AsA + ((wm * 32 + mi * 16 + (lane & 15)) * GS +
                                    ((lane >> 4) & 1) * 8 + ks * 16) * 2;
                ldsm4(a, af[mi][0], af[mi][1], af[mi][2], af[mi][3]);
            }
#pragma unroll
            for (int j = 0; j < 4; j++) {
                uint32_t b0, b1, b2, b3;
                uint32_t a = WsA + ((wn * 64 + j * 16 + (lane & 7) + (lane >> 4) * 8) * GS +
                                    ((lane >> 3) & 1) * 8 + ks * 16) * 2;
                ldsm4(a, b0, b1, b2, b3);
#pragma unroll
                for (int mi = 0; mi < 2; mi++) {
                    mma_bf16(acc[mi][2 * j],     af[mi], b0, b1);
                    mma_bf16(acc[mi][2 * j + 1], af[mi], b2, b3);
                }
            }
        }
        __syncthreads();
    }

#pragma unroll
    for (int mi = 0; mi < 2; mi++) {
        const int r = mBase + wm * 32 + mi * 16 + gid;
#pragma unroll
        for (int nj = 0; nj < 8; nj++) {
            const int c = nBase + wn * 64 + nj * 8 + 2 * t4;
            store2(C, (size_t)r * DD + c,       acc[mi][nj][0], acc[mi][nj][1]);
            store2(C, (size_t)(r + 8) * DD + c, acc[mi][nj][2], acc[mi][nj][3]);
        }
    }
}

// ---------------- Flash attention (bf16, ldmatrix, cp.async double buffer) ----
#define SKV 136
#define TSZ (128 * SKV)
#define ATT_SMEM_BYTES (5 * TSZ * 2)

__global__ void __launch_bounds__(256, 1)
attn_kernel(const __nv_bfloat16* __restrict__ Q, const __nv_bfloat16* __restrict__ K,
            const __nv_bfloat16* __restrict__ V, __nv_bfloat16* __restrict__ O) {
    extern __shared__ __nv_bfloat16 smb[];
    __nv_bfloat16* Qs = smb;
    __nv_bfloat16* KsA[2] = {smb + TSZ, smb + 2 * TSZ};
    __nv_bfloat16* VsA[2] = {smb + 3 * TSZ, smb + 4 * TSZ};

    const int tid  = threadIdx.x;
    const int warp = tid >> 5;
    const int lane = tid & 31;
    const int gid  = lane >> 2;
    const int t4   = lane & 3;

    const int g  = blockIdx.y;
    const int qt = blockIdx.x;

    const __nv_bfloat16* Qg = Q + (size_t)g * SS * CH + (size_t)qt * 128 * CH;
    const __nv_bfloat16* Kg = K + (size_t)g * SS * CH;
    const __nv_bfloat16* Vg = V + (size_t)g * SS * CH;
    __nv_bfloat16*       Og = O + (size_t)g * SS * CH + (size_t)qt * 128 * CH;

    const int col8 = (tid & 15) * 8;
    const int r0   = tid >> 4;

#pragma unroll
    for (int i = 0; i < 8; i++) {
        const int r = r0 + i * 16;
        *(uint4*)(Qs + r * SKV + col8) = *(const uint4*)(Qg + (size_t)r * CH + col8);
    }

    {
#pragma unroll
        for (int i = 0; i < 8; i++) {
            const int r = r0 + i * 16;
            cp16(smem_u32(KsA[0] + r * SKV + col8), Kg + (size_t)r * CH + col8);
            cp16(smem_u32(VsA[0] + r * SKV + col8), Vg + (size_t)r * CH + col8);
        }
        asm volatile("cp.async.commit_group;");
    }
    __syncthreads();

    // preload Q fragments and fold in softmax scale (2^-5: exact in bf16)
    const uint32_t sc2 = packbf2(SCALE, SCALE);
    uint32_t qf[8][4];
#pragma unroll
    for (int ks = 0; ks < 8; ks++) {
        uint32_t a = smem_u32(Qs) + ((warp * 16 + (lane & 15)) * SKV +
                                     ((lane >> 4) & 1) * 8 + ks * 16) * 2;
        ldsm4(a, qf[ks][0], qf[ks][1], qf[ks][2], qf[ks][3]);
#pragma unroll
        for (int q = 0; q < 4; q++) qf[ks][q] = mul_bf16x2(qf[ks][q], sc2);
    }

    float oc[16][4];
#pragma unroll
    for (int j = 0; j < 16; j++)
#pragma unroll
        for (int q = 0; q < 4; q++) oc[j][q] = 0.0f;
    float m1 = -1e30f, m2 = -1e30f, l1 = 0.0f, l2 = 0.0f;

    for (int kt = 0; kt < 16; kt++) {
        if (kt < 15) {
            const __nv_bfloat16* Kt = Kg + (size_t)(kt + 1) * 128 * CH;
            const __nv_bfloat16* Vt = Vg + (size_t)(kt + 1) * 128 * CH;
            __nv_bfloat16* Kd = KsA[(kt + 1) & 1];
            __nv_bfloat16* Vd = VsA[(kt + 1) & 1];
#pragma unroll
            for (int i = 0; i < 8; i++) {
                const int r = r0 + i * 16;
                cp16(smem_u32(Kd + r * SKV + col8), Kt + (size_t)r * CH + col8);
                cp16(smem_u32(Vd + r * SKV + col8), Vt + (size_t)r * CH + col8);
            }
            asm volatile("cp.async.commit_group;");
            asm volatile("cp.async.wait_group 1;");
        } else {
            asm volatile("cp.async.wait_group 0;");
        }
        __syncthreads();

        const uint32_t Kbase = smem_u32(KsA[kt & 1]);
        const uint32_t Vbase = smem_u32(VsA[kt & 1]);

        float sc[16][4];
#pragma unroll
        for (int j = 0; j < 16; j++)
#pragma unroll
            for (int q = 0; q < 4; q++) sc[j][q] = 0.0f;

#pragma unroll
        for (int ks = 0; ks < 8; ks++) {
#pragma unroll
            for (int j = 0; j < 8; j++) {
                uint32_t b0, b1, b2, b3;
                uint32_t a = Kbase + ((j * 16 + (lane & 7) + (lane >> 4) * 8) * SKV +
                                      ((lane >> 3) & 1) * 8 + ks * 16) * 2;
                ldsm4(a, b0, b1, b2, b3);
                mma_bf16(sc[2 * j],     qf[ks], b0, b1);
                mma_bf16(sc[2 * j + 1], qf[ks], b2, b3);
            }
        }

        float rmax1 = -1e30f, rmax2 = -1e30f;
#pragma unroll
        for (int j = 0; j < 16; j++) {
            rmax1 = fmaxf(rmax1, fmaxf(sc[j][0], sc[j][1]));
            rmax2 = fmaxf(rmax2, fmaxf(sc[j][2], sc[j][3]));
        }
        rmax1 = fmaxf(rmax1, __shfl_xor_sync(0xffffffffu, rmax1, 1));
        rmax1 = fmaxf(rmax1, __shfl_xor_sync(0xffffffffu, rmax1, 2));
        rmax2 = fmaxf(rmax2, __shfl_xor_sync(0xffffffffu, rmax2, 1));
        rmax2 = fmaxf(rmax2, __shfl_xor_sync(0xffffffffu, rmax2, 2));

        const float mn1 = fmaxf(m1, rmax1);
        const float mn2 = fmaxf(m2, rmax2);
        const float al1 = __expf(m1 - mn1);
        const float al2 = __expf(m2 - mn2);
        m1 = mn1; m2 = mn2;

        float s1 = 0.0f, s2 = 0.0f;
#pragma unroll
        for (int j = 0; j < 16; j++) {
            sc[j][0] = __expf(sc[j][0] - mn1);
            sc[j][1] = __expf(sc[j][1] - mn1);
            sc[j][2] = __expf(sc[j][2] - mn2);
            sc[j][3] = __expf(sc[j][3] - mn2);
            s1 += sc[j][0] + sc[j][1];
            s2 += sc[j][2] + sc[j][3];
        }
        s1 += __shfl_xor_sync(0xffffffffu, s1, 1);
        s1 += __shfl_xor_sync(0xffffffffu, s1, 2);
        s2 += __shfl_xor_sync(0xffffffffu, s2, 1);
        s2 += __shfl_xor_sync(0xffffffffu, s2, 2);
        l1 = l1 * al1 + s1;
        l2 = l2 * al2 + s2;

#pragma unroll
        for (int j = 0; j < 16; j++) {
            oc[j][0] *= al1; oc[j][1] *= al1;
            oc[j][2] *= al2; oc[j][3] *= al2;
        }

        uint32_t pf[8][4];
#pragma unroll
        for (int kk = 0; kk < 8; kk++) {
            pf[kk][0] = packbf2(sc[2 * kk][0],     sc[2 * kk][1]);
            pf[kk][1] = packbf2(sc[2 * kk][2],     sc[2 * kk][3]);
            pf[kk][2] = packbf2(sc[2 * kk + 1][0], sc[2 * kk + 1][1]);
            pf[kk][3] = packbf2(sc[2 * kk + 1][2], sc[2 * kk + 1][3]);
        }

#pragma unroll
        for (int kk = 0; kk < 8; kk++) {
#pragma unroll
            for (int j = 0; j < 8; j++) {
                uint32_t b0, b1, b2, b3;
                uint32_t a = Vbase + ((kk * 16 + (lane & 7) + ((lane >> 3) & 1) * 8) * SKV +
                                      j * 16 + (lane >> 4) * 8) * 2;
                ldsm4t(a, b0, b1, b2, b3);
                mma_bf16(oc[2 * j],     pf[kk], b0, b1);
                mma_bf16(oc[2 * j + 1], pf[kk], b2, b3);
            }
        }
        __syncthreads();
    }

    const float inv1 = 1.0f / l1;
    const float inv2 = 1.0f / l2;
    const int qr = warp * 16 + gid;
#pragma unroll
    for (int j = 0; j < 16; j++) {
        const int c = j * 8 + 2 * t4;
        *(__nv_bfloat162*)(Og + (size_t)qr * CH + c) =
            __floats2bfloat162_rn(oc[j][0] * inv1, oc[j][1] * inv1);
        *(__nv_bfloat162*)(Og + (size_t)(qr + 8) * CH + c) =
            __floats2bfloat162_rn(oc[j][2] * inv2, oc[j][3] * inv2);
    }
}

// ---------------- bias + residual + LayerNorm ----------------
__global__ __launch_bounds__(256) void ln_kernel(const float* __restrict__ P,
                                                 const float* __restrict__ X,
                                                 const float* __restrict__ bp,
                                                 const float* __restrict__ gamma,
                                                 const float* __restrict__ beta,
                                                 float* __restrict__ out) {
    const int row = blockIdx.x;
    const int tid = threadIdx.x;

    float4 pv = ((const float4*)(P + (size_t)row * DD))[tid];
    float4 xv = ((const float4*)(X + (size_t)row * DD))[tid];
    float4 bv = ((const float4*)bp)[tid];
    float4 v;
    v.x = pv.x + xv.x + bv.x;
    v.y = pv.y + xv.y + bv.y;
    v.z = pv.z + xv.z + bv.z;
    v.w = pv.w + xv.w + bv.w;

    float s  = v.x + v.y + v.z + v.w;
    float sq = v.x * v.x + v.y * v.y + v.z * v.z + v.w * v.w;
#pragma unroll
    for (int o = 16; o > 0; o >>= 1) {
        s  += __shfl_xor_sync(0xffffffffu, s, o);
        sq += __shfl_xor_sync(0xffffffffu, sq, o);
    }
    __shared__ float ss[8], ssq[8];
    const int warp = tid >> 5;
    if ((tid & 31) == 0) { ss[warp] = s; ssq[warp] = sq; }
    __syncthreads();
    if (tid == 0) {
        float ts = 0.0f, tq = 0.0f;
#pragma unroll
        for (int w = 0; w < 8; w++) { ts += ss[w]; tq += ssq[w]; }
        ss[0] = ts; ssq[0] = tq;
    }
    __syncthreads();
    const float mean = ss[0] * (1.0f / DD);
    const float var  = ssq[0] * (1.0f / DD) - mean * mean;
    const float rstd = rsqrtf(var + LN_EPS);

    float4 gv = ((const float4*)gamma)[tid];
    float4 bt = ((const float4*)beta)[tid];
    float4 o;
    o.x = (v.x - mean) * rstd * gv.x + bt.x;
    o.y = (v.y - mean) * rstd * gv.y + bt.y;
    o.z = (v.z - mean) * rstd * gv.z + bt.z;
    o.w = (v.w - mean) * rstd * gv.w + bt.w;
    ((float4*)(out + (size_t)row * DD))[tid] = o;
}

// ---------------- launch ----------------
extern "C" void kernel_launch(void* const* d_in, const int* in_sizes, int n_in,
                              void* d_out, int out_size) {
    const float* query = (const float*)d_in[0];
    const float* keys  = (const float*)d_in[1];
    const float* Wq    = (const float*)d_in[2];
    const float* Wk    = (const float*)d_in[3];
    const float* Wv    = (const float*)d_in[4];
    const float* Wp    = (const float*)d_in[5];
    const float* bp    = (const float*)d_in[6];
    const float* ln_g  = (const float*)d_in[7];
    const float* ln_b  = (const float*)d_in[8];
    float* out = (float*)d_out;

    __nv_bfloat16 *pAq, *pAk, *pWq, *pWk, *pWv, *pWp, *pQ, *pK, *pV, *pC;
    float *pO;
    cudaGetSymbolAddress((void**)&pAq, g_Aq);
    cudaGetSymbolAddress((void**)&pAk, g_Ak);
    cudaGetSymbolAddress((void**)&pWq, g_Wqb);
    cudaGetSymbolAddress((void**)&pWk, g_Wkb);
    cudaGetSymbolAddress((void**)&pWv, g_Wvb);
    cudaGetSymbolAddress((void**)&pWp, g_Wpb);
    cudaGetSymbolAddress((void**)&pQ,  g_Qb);
    cudaGetSymbolAddress((void**)&pK,  g_Kb);
    cudaGetSymbolAddress((void**)&pV,  g_Vb);
    cudaGetSymbolAddress((void**)&pC,  g_Cb);
    cudaGetSymbolAddress((void**)&pO,  g_O);

    cudaFuncSetAttribute(attn_kernel, cudaFuncAttributeMaxDynamicSharedMemorySize,
                         ATT_SMEM_BYTES);
    cudaFuncSetAttribute(gemm_pl<__nv_bfloat16>, cudaFuncAttributeMaxDynamicSharedMemorySize,
                         GEMM_SMEM_BYTES);
    cudaFuncSetAttribute(gemm_pl<float>, cudaFuncAttributeMaxDynamicSharedMemorySize,
                         GEMM_SMEM_BYTES);

    // fp32 -> bf16 conversions (once; removes converts + halves traffic in GEMMs)
    const int n4a = (MM * DD) / 4;
    const int n4w = (DD * DD) / 4;
    f2bf_kernel<<<n4a / 256, 256>>>((const float4*)query, (uint2*)pAq, n4a);
    f2bf_kernel<<<n4a / 256, 256>>>((const float4*)keys,  (uint2*)pAk, n4a);
    f2bf_kernel<<<n4w / 256, 256>>>((const float4*)Wq, (uint2*)pWq, n4w);
    f2bf_kernel<<<n4w / 256, 256>>>((const float4*)Wk, (uint2*)pWk, n4w);
    f2bf_kernel<<<n4w / 256, 256>>>((const float4*)Wv, (uint2*)pWv, n4w);
    f2bf_kernel<<<n4w / 256, 256>>>((const float4*)Wp, (uint2*)pWp, n4w);

    dim3 ggrid(DD / 128, MM / 128);  // (8, 128)
    gemm_pl<__nv_bfloat16><<<ggrid, 256, GEMM_SMEM_BYTES>>>(pAq, pWq, pQ);
    gemm_pl<__nv_bfloat16><<<ggrid, 256, GEMM_SMEM_BYTES>>>(pAk, pWk, pK);
    gemm_pl<__nv_bfloat16><<<ggrid, 256, GEMM_SMEM_BYTES>>>(pAk, pWv, pV);

    attn_kernel<<<dim3(SS / 128, GG), 256, ATT_SMEM_BYTES>>>(pQ, pK, pV, pC);

    gemm_pl<float><<<ggrid, 256, GEMM_SMEM_BYTES>>>(pC, pWp, pO);

    ln_kernel<<<MM, 256>>>(pO, query, bp, ln_g, ln_b, out);
}